// round 12
// baseline (speedup 1.0000x reference)
#include <cuda_runtime.h>
#include <cuda_fp16.h>
#include <math.h>
#include <stdint.h>

#define B_ 4
#define T_ 4096
#define C_ 1024
#define H_ 128
#define M_ (B_ * T_)

// fp16 scratch (no cudaMalloc allowed)
__device__ __half g_k[M_ * H_];
__device__ __half g_q[M_ * H_];
__device__ __half g_v[M_ * H_];
__device__ __half g_wh[3 * C_ * H_];

// log2(e) / 32  (softmax done in exp2 domain)
#define SM_SCALE 0.04508422f

__device__ __forceinline__ uint32_t sptr(const void* p) {
    return (uint32_t)__cvta_generic_to_shared(p);
}
__device__ __forceinline__ uint32_t pkh2(float a, float b) {
    __half2 h = __floats2half2_rn(a, b);
    return *reinterpret_cast<uint32_t*>(&h);
}
__device__ __forceinline__ float ex2(float x) {
    float y;
    asm("ex2.approx.f32 %0, %1;" : "=f"(y) : "f"(x));
    return y;
}
__device__ __forceinline__ void ldsm_x4(uint32_t* r, uint32_t a) {
    asm volatile("ldmatrix.sync.aligned.m8n8.x4.shared.b16 {%0,%1,%2,%3}, [%4];"
                 : "=r"(r[0]), "=r"(r[1]), "=r"(r[2]), "=r"(r[3]) : "r"(a));
}
__device__ __forceinline__ void ldsm_x4t(uint32_t* r, uint32_t a) {
    asm volatile("ldmatrix.sync.aligned.m8n8.x4.trans.shared.b16 {%0,%1,%2,%3}, [%4];"
                 : "=r"(r[0]), "=r"(r[1]), "=r"(r[2]), "=r"(r[3]) : "r"(a));
}
__device__ __forceinline__ void mma16(float* c, const uint32_t* a, const uint32_t* b) {
    asm volatile(
        "mma.sync.aligned.m16n8k16.row.col.f32.f16.f16.f32 "
        "{%0,%1,%2,%3},{%4,%5,%6,%7},{%8,%9},{%0,%1,%2,%3};"
        : "+f"(c[0]), "+f"(c[1]), "+f"(c[2]), "+f"(c[3])
        : "r"(a[0]), "r"(a[1]), "r"(a[2]), "r"(a[3]), "r"(b[0]), "r"(b[1]));
}
__device__ __forceinline__ void barg(int id) {
    asm volatile("bar.sync %0, 128;" ::"r"(id) : "memory");
}
__device__ __forceinline__ void cpa16(uint32_t s, const void* g) {
    asm volatile("cp.async.cg.shared.global [%0], [%1], 16;" ::"r"(s), "l"(g));
}
__device__ __forceinline__ void cpcommit() { asm volatile("cp.async.commit_group;"); }
template <int N>
__device__ __forceinline__ void cpwait() {
    asm volatile("cp.async.wait_group %0;" ::"n"(N));
}

// ---------------------------------------------------------------------------
// W converter: Wk|Wq|Wv fp32 -> g_wh fp16. grid 384 x 256 = exactly 1 elem/thread.
// ---------------------------------------------------------------------------
__global__ __launch_bounds__(256) void wconv_kernel(const float* __restrict__ Wk,
                                                    const float* __restrict__ Wq,
                                                    const float* __restrict__ Wv) {
    int idx = blockIdx.x * 256 + threadIdx.x;  // float4 index, 98304 total
    int mat = idx >> 15;
    int rem = idx & 32767;
    const float* src = (mat == 0) ? Wk : (mat == 1) ? Wq : Wv;
    float4 v = *(const float4*)&src[rem * 4];
    uint2 u = make_uint2(pkh2(v.x, v.y), pkh2(v.z, v.w));
    *(uint2*)&g_wh[(size_t)mat * C_ * H_ + rem * 4] = u;
}

// ---------------------------------------------------------------------------
// Triple projection: 12 warps = (3 mats x 2 wm x 2 wn); warp owns 32 rows x
// 64 cols of one matrix. x loaded+converted once; W fp16 streamed from g_wh.
// ---------------------------------------------------------------------------
#define XP_S 40
#define WP_S 136
#define PJ_XF(b) ((b) * 8192)            // 64x32 f32 = 8 KB per buf
#define PJ_XS 16384                      // 64*XP_S halves = 5120 B
#define PJ_WS(b) (21504 + (b) * 26112)   // 3*32*WP_S halves = 26112 B per buf
#define PJ_SMEM (21504 + 2 * 26112)

__global__ __launch_bounds__(384) void proj_kernel(const float* __restrict__ x) {
    extern __shared__ char psm[];
    __half* Xs = (__half*)(psm + PJ_XS);

    const int tid  = threadIdx.x;
    const int warp = tid >> 5;
    const int lane = tid & 31;
    const int g    = lane >> 2;
    const int q    = lane & 3;
    const int mt   = warp >> 2;        // matrix 0..2
    const int wm   = (warp >> 1) & 1;  // 32-row strip
    const int wn   = warp & 1;         // 64-col half
    const int m0   = blockIdx.x * 64;

    float acc[2][8][4];
#pragma unroll
    for (int mf = 0; mf < 2; mf++)
#pragma unroll
        for (int nb = 0; nb < 8; nb++)
#pragma unroll
            for (int k = 0; k < 4; k++) acc[mf][nb][k] = 0.0f;

    auto pref = [&](int it, int bi) {
        int k0 = it * 32;
        // x slab: 512 16B chunks
#pragma unroll
        for (int t = 0; t < 2; t++) {
            int id = tid + t * 384;
            if (id < 512) {
                int row = id >> 3, c4 = id & 7;
                cpa16(sptr(psm + PJ_XF(bi) + id * 16), &x[(size_t)(m0 + row) * C_ + k0 + c4 * 4]);
            }
        }
        // W chunk (3 mats x 32 x 128 halves): 1536 = 4*384 16B chunks
#pragma unroll
        for (int t = 0; t < 4; t++) {
            int id = tid + t * 384;
            int mat = id >> 9, rem = id & 511;
            int row = rem >> 4, c8 = rem & 15;
            cpa16(sptr(psm + PJ_WS(bi) + ((mat * 32 + row) * WP_S + c8 * 8) * 2),
                  &g_wh[(size_t)mat * C_ * H_ + (size_t)(k0 + row) * H_ + c8 * 8]);
        }
    };

    pref(0, 0);
    cpcommit();

    for (int it = 0; it < 32; it++) {
        const int bi = it & 1;
        if (it + 1 < 32) pref(it + 1, bi ^ 1);
        cpcommit();
        cpwait<1>();
        __syncthreads();

        // convert x staging fp32 -> fp16 tile (1024 pairs)
        const float* Xf = (const float*)(psm + PJ_XF(bi));
#pragma unroll
        for (int t = 0; t < 3; t++) {
            int p = tid + t * 384;
            if (p < 1024) {
                float2 v = *(const float2*)&Xf[2 * p];
                int row = p >> 4, cp = p & 15;
                *(uint32_t*)&Xs[row * XP_S + 2 * cp] = pkh2(v.x, v.y);
            }
        }
        __syncthreads();

        const __half* Ws = (const __half*)(psm + PJ_WS(bi));
#pragma unroll
        for (int kst = 0; kst < 2; kst++) {
            uint32_t a[2][4];
#pragma unroll
            for (int mf = 0; mf < 2; mf++) {
                int r  = wm * 32 + mf * 16 + (lane & 15);
                int cc = kst * 16 + (lane >> 4) * 8;
                ldsm_x4(a[mf], sptr(&Xs[r * XP_S + cc]));
            }
            int vr = kst * 16 + (lane & 7) + 8 * ((lane >> 3) & 1);
#pragma unroll
            for (int nb2 = 0; nb2 < 4; nb2++) {
                uint32_t bfr[4];
                int col = wn * 64 + (2 * nb2 + (lane >> 4)) * 8;
                ldsm_x4t(bfr, sptr(&Ws[(mt * 32 + vr) * WP_S + col]));
                mma16(acc[0][2 * nb2], a[0], bfr);
                mma16(acc[0][2 * nb2 + 1], a[0], bfr + 2);
                mma16(acc[1][2 * nb2], a[1], bfr);
                mma16(acc[1][2 * nb2 + 1], a[1], bfr + 2);
            }
        }
        __syncthreads();  // all warps done reading Ws[bi] before it is re-prefetched
    }
    cpwait<0>();

    {
        __half* y = (mt == 0) ? g_k : (mt == 1) ? g_q : g_v;
#pragma unroll
        for (int mf = 0; mf < 2; mf++) {
            int row = m0 + wm * 32 + mf * 16 + g;
#pragma unroll
            for (int nb = 0; nb < 8; nb++) {
                int col = wn * 64 + nb * 8 + 2 * q;
                *(uint32_t*)&y[(size_t)row * H_ + col] = pkh2(acc[mf][nb][0], acc[mf][nb][1]);
                *(uint32_t*)&y[(size_t)(row + 8) * H_ + col] = pkh2(acc[mf][nb][2], acc[mf][nb][3]);
            }
        }
    }
}

// ---------------------------------------------------------------------------
// Flash attention: fp16 m16n8k16, 3 phase-shifted 4-warp groups (384 thr),
// cp.async double-buffered Q/V per group, exp2 softmax, x4 ldmatrix operands.
// ---------------------------------------------------------------------------
#define AGRID 148
#define KQ_SH 136
#define TILE_H (64 * KQ_SH)
#define ASMEM_HALVES (13 * TILE_H)       // K + 3 groups x 2 bufs x (Q,V)
#define ASMEM_BYTES  (ASMEM_HALVES * 2)  // 226304 B
#define MRG_S 132

__global__ __launch_bounds__(384) void attn_kernel(float* __restrict__ out) {
    extern __shared__ __half smh[];
    __half* Ks = smh;
    const int tid  = threadIdx.x;
    const int warp = tid >> 5;
    const int lane = tid & 31;
    const int gr   = warp >> 2;       // group 0..2
    const int w    = warp & 3;
    const int tg   = tid & 127;
    const int g    = lane >> 2;
    const int q    = lane & 3;
    const int rA   = w * 16 + g;
    const int barid = gr + 1;

    __half* GB = Ks + TILE_H + gr * 4 * TILE_H;  // [Q0,V0,Q1,V1]
    float* F1 = (float*)(Ks + TILE_H * 5);       // group1 buffers (merge scratch)
    float* F2 = (float*)(Ks + TILE_H * 9);       // group2 buffers

    const int c = blockIdx.x;

    for (int u = 0; u < 2; u++) {
        if (u == 1 && c >= 256 - AGRID) break;
        const int idx    = (u == 0) ? c : 255 - c;
        const int i_tile = 63 - (idx >> 2);
        const int b      = idx & 3;
        const int i0     = i_tile * 64;
        const int nj     = i_tile + 1;

        __syncthreads();  // prior unit fully done with smem

        // K tile via cp.async (1024 chunks)
        {
            const uint4* ksrc = (const uint4*)(g_k + ((size_t)b * T_ + i0) * H_);
#pragma unroll
            for (int t = 0; t < 3; t++) {
                int id = tid + t * 384;
                if (id < 1024) {
                    int row = id >> 4, c8 = id & 15;
                    cpa16(sptr(&Ks[row * KQ_SH + c8 * 8]), ksrc + id);
                }
            }
        }
        cpcommit();

        auto pref = [&](int jt, int bi) {
            const uint4* qsrc = (const uint4*)(g_q + ((size_t)b * T_ + jt * 64) * H_);
            const uint4* vsrc = (const uint4*)(g_v + ((size_t)b * T_ + jt * 64) * H_);
            __half* Qd = GB + bi * 2 * TILE_H;
            __half* Vd = Qd + TILE_H;
#pragma unroll
            for (int t = 0; t < 8; t++) {
                int id = tg + t * 128;
                int row = id >> 4, c8 = id & 15;
                cpa16(sptr(&Qd[row * KQ_SH + c8 * 8]), qsrc + id);
                cpa16(sptr(&Vd[row * KQ_SH + c8 * 8]), vsrc + id);
            }
        };

        if (gr < nj) pref(gr, 0);
        cpcommit();
        if (gr < nj) cpwait<1>(); else cpwait<0>();
        __syncthreads();  // K landed for everyone

        float o[16][4];
#pragma unroll
        for (int hb = 0; hb < 16; hb++)
#pragma unroll
            for (int k = 0; k < 4; k++) o[hb][k] = 0.0f;
        float mrow[2] = {-1e30f, -1e30f};
        float lrow[2] = {0.0f, 0.0f};

        int pf = 1;
        for (int jt = gr; jt < nj; jt += 3) {
            const int j0 = jt * 64;
            barg(barid);
            if (jt + 3 < nj) pref(jt + 3, pf);
            cpcommit();
            cpwait<1>();
            barg(barid);

            const __half* Qs = GB + (pf ^ 1) * 2 * TILE_H;
            const __half* Vs = Qs + TILE_H;
            pf ^= 1;

            // ---- S = K @ Q^T (x4 B loads: 2 n-blocks per ldmatrix) ----
            float s[8][4];
#pragma unroll
            for (int nb = 0; nb < 8; nb++)
#pragma unroll
                for (int k = 0; k < 4; k++) s[nb][k] = 0.0f;
#pragma unroll
            for (int kst = 0; kst < 8; kst++) {
                uint32_t a[4];
                int cc = kst * 16 + (lane >> 4) * 8;
                ldsm_x4(a, sptr(&Ks[(w * 16 + (lane & 15)) * KQ_SH + cc]));
                int qcc = kst * 16 + ((lane >> 3) & 1) * 8;
#pragma unroll
                for (int nb2 = 0; nb2 < 4; nb2++) {
                    uint32_t bq[4];
                    int qr = (2 * nb2 + (lane >> 4)) * 8 + (lane & 7);
                    ldsm_x4(bq, sptr(&Qs[qr * KQ_SH + qcc]));
                    mma16(s[2 * nb2], a, bq);
                    mma16(s[2 * nb2 + 1], a, bq + 2);
                }
            }

            // ---- scale (exp2 domain) + causal mask ----
            const bool diag = (jt == i_tile);
#pragma unroll
            for (int nb = 0; nb < 8; nb++) {
                int jc = j0 + nb * 8 + 2 * q;
                int riA = i0 + rA, riB = riA + 8;
                float v0 = s[nb][0] * SM_SCALE, v1 = s[nb][1] * SM_SCALE;
                float v2 = s[nb][2] * SM_SCALE, v3 = s[nb][3] * SM_SCALE;
                if (diag) {
                    if (jc > riA) v0 = -1e30f;
                    if (jc + 1 > riA) v1 = -1e30f;
                    if (jc > riB) v2 = -1e30f;
                    if (jc + 1 > riB) v3 = -1e30f;
                }
                s[nb][0] = v0; s[nb][1] = v1; s[nb][2] = v2; s[nb][3] = v3;
            }

            // ---- online softmax (exp2) ----
#pragma unroll
            for (int t = 0; t < 2; t++) {
                float tm = -1e30f;
#pragma unroll
                for (int nb = 0; nb < 8; nb++)
                    tm = fmaxf(tm, fmaxf(s[nb][2 * t], s[nb][2 * t + 1]));
                tm = fmaxf(tm, __shfl_xor_sync(0xffffffffu, tm, 1));
                tm = fmaxf(tm, __shfl_xor_sync(0xffffffffu, tm, 2));
                float mn = fmaxf(mrow[t], tm);
                float sc = ex2(mrow[t] - mn);
                mrow[t] = mn;
                float rs = 0.0f;
#pragma unroll
                for (int nb = 0; nb < 8; nb++) {
                    float p0 = ex2(s[nb][2 * t] - mn);
                    float p1 = ex2(s[nb][2 * t + 1] - mn);
                    s[nb][2 * t] = p0; s[nb][2 * t + 1] = p1;
                    rs += p0 + p1;
                }
                rs += __shfl_xor_sync(0xffffffffu, rs, 1);
                rs += __shfl_xor_sync(0xffffffffu, rs, 2);
                lrow[t] = lrow[t] * sc + rs;
#pragma unroll
                for (int hb = 0; hb < 16; hb++) {
                    o[hb][2 * t] *= sc; o[hb][2 * t + 1] *= sc;
                }
            }

            // ---- P fragments from registers ----
            uint32_t pa[4][4];
#pragma unroll
            for (int kt = 0; kt < 4; kt++) {
                pa[kt][0] = pkh2(s[2 * kt][0], s[2 * kt][1]);
                pa[kt][1] = pkh2(s[2 * kt][2], s[2 * kt][3]);
                pa[kt][2] = pkh2(s[2 * kt + 1][0], s[2 * kt + 1][1]);
                pa[kt][3] = pkh2(s[2 * kt + 1][2], s[2 * kt + 1][3]);
            }

            // ---- O += P @ V (x4 trans loads: 2 h-blocks per ldmatrix) ----
#pragma unroll
            for (int kt = 0; kt < 4; kt++) {
                int vr = kt * 16 + (lane & 7) + 8 * ((lane >> 3) & 1);
#pragma unroll
                for (int hb2 = 0; hb2 < 8; hb2++) {
                    uint32_t bv[4];
                    int col = (2 * hb2 + (lane >> 4)) * 8;
                    ldsm_x4t(bv, sptr(&Vs[vr * KQ_SH + col]));
                    mma16(o[2 * hb2], pa[kt], bv);
                    mma16(o[2 * hb2 + 1], pa[kt], bv + 2);
                }
            }
        }
        cpwait<0>();
        barg(barid);  // group fully done with its buffers

        // ---- 3-way merge; group 0 writes final ----
        if (gr >= 1) {
            float* F = (gr == 1) ? F1 : F2;
#pragma unroll
            for (int t = 0; t < 2; t++) {
                int r = rA + t * 8;
                if (q == 0) { F[r] = mrow[t]; F[64 + r] = lrow[t]; }
#pragma unroll
                for (int hb = 0; hb < 16; hb++) {
                    *(float2*)&F[128 + r * MRG_S + hb * 8 + 2 * q] =
                        make_float2(o[hb][2 * t], o[hb][2 * t + 1]);
                }
            }
        }
        __syncthreads();
        if (gr == 0) {
#pragma unroll
            for (int t = 0; t < 2; t++) {
                int r = rA + t * 8;
                float m1 = F1[r], l1 = F1[64 + r];
                float m2 = F2[r], l2 = F2[64 + r];
                float mm = fmaxf(mrow[t], fmaxf(m1, m2));
                float f0 = ex2(mrow[t] - mm);
                float f1 = ex2(m1 - mm);
                float f2 = ex2(m2 - mm);
                float inv = 1.0f / (lrow[t] * f0 + l1 * f1 + l2 * f2);
                size_t rbase = ((size_t)b * T_ + i0 + r) * H_;
#pragma unroll
                for (int hb = 0; hb < 16; hb++) {
                    float2 o1 = *(const float2*)&F1[128 + r * MRG_S + hb * 8 + 2 * q];
                    float2 o2 = *(const float2*)&F2[128 + r * MRG_S + hb * 8 + 2 * q];
                    *(float2*)&out[rbase + hb * 8 + 2 * q] =
                        make_float2((o[hb][2 * t] * f0 + o1.x * f1 + o2.x * f2) * inv,
                                    (o[hb][2 * t + 1] * f0 + o1.y * f1 + o2.y * f2) * inv);
                }
            }
        }
    }
}

// ---------------------------------------------------------------------------
extern "C" void kernel_launch(void* const* d_in, const int* in_sizes, int n_in,
                              void* d_out, int out_size) {
    const float* x  = (const float*)d_in[0];
    const float* Wk = (const float*)d_in[1];
    const float* Wq = (const float*)d_in[2];
    const float* Wv = (const float*)d_in[3];
    float* out = (float*)d_out;

    cudaFuncSetAttribute(proj_kernel, cudaFuncAttributeMaxDynamicSharedMemorySize, PJ_SMEM);
    cudaFuncSetAttribute(attn_kernel, cudaFuncAttributeMaxDynamicSharedMemorySize, ASMEM_BYTES);

    wconv_kernel<<<384, 256>>>(Wk, Wq, Wv);
    proj_kernel<<<M_ / 64, 384, PJ_SMEM>>>(x);
    attn_kernel<<<AGRID, 384, ASMEM_BYTES>>>(out);
}